// round 7
// baseline (speedup 1.0000x reference)
#include <cuda_runtime.h>
#include <cstdint>

// Problem dims (fixed)
#define NB   64
#define NC   256
#define NCI  128
#define NTOK 256
#define NH   64

// -------------------- device scratch --------------------
__device__ float g_xp  [NB * NC  * NTOK];   // pooled [b][c][tok]
__device__ float g_Wtp [NC * 256];          // [c][r]  r = theta|phi
__device__ float g_gwT [NC * NCI];          // [c][cc]
__device__ float g_owT [NCI * NC];          // [cc][C]
__device__ float g_btp [256];
__device__ float g_proj[NB * 256 * NTOK];   // theta|phi, [r][tok]
__device__ float g_gT  [NB * NTOK * NCI];   // [tok][cc]
__device__ float g_attn[NB * NTOK * NTOK];  // attnT [j][i]
__device__ float g_agg [NB * NCI * NTOK];   // aggT [cc][tok]

// -------------------- mma + cp.async helpers --------------------
__device__ __forceinline__ void mma_tf32(float (&c)[4],
                                         uint32_t a0, uint32_t a1, uint32_t a2, uint32_t a3,
                                         uint32_t b0, uint32_t b1) {
    asm volatile(
        "mma.sync.aligned.m16n8k8.row.col.f32.tf32.tf32.f32 "
        "{%0,%1,%2,%3},{%4,%5,%6,%7},{%8,%9},{%0,%1,%2,%3};\n"
        : "+f"(c[0]), "+f"(c[1]), "+f"(c[2]), "+f"(c[3])
        : "r"(a0), "r"(a1), "r"(a2), "r"(a3), "r"(b0), "r"(b1));
}
#define CPA(dst, src) asm volatile("cp.async.cg.shared.global [%0], [%1], 16;" :: "r"(dst), "l"(src))
#define CPC()         asm volatile("cp.async.commit_group;")
#define CPW(n)        asm volatile("cp.async.wait_group %0;" :: "n"(n))

// -------------------- weight prep --------------------
__global__ void concat_weights(const float* __restrict__ tw, const float* __restrict__ tb,
                               const float* __restrict__ pw, const float* __restrict__ pb,
                               const float* __restrict__ gw, const float* __restrict__ ow) {
    int idx = blockIdx.x * 256 + threadIdx.x;
    if (idx < 65536) {
        int c = idx >> 8, r = idx & 255;
        g_Wtp[idx] = (r < 128) ? tw[r * NC + c] : pw[(r - 128) * NC + c];
        if (idx < 256) g_btp[idx] = (idx < 128) ? tb[idx] : pb[idx - 128];
    } else if (idx < 65536 + 32768) {
        int j = idx - 65536;
        int c = j >> 7, cc = j & 127;
        g_gwT[j] = gw[cc * NC + c];
    } else {
        int j = idx - 65536 - 32768;
        int cc = j >> 8, C = j & 255;
        g_owT[j] = ow[C * NCI + cc];
    }
}

// -------------------- 4x4 avg pool --------------------
__global__ void pool_kernel(const float* __restrict__ x) {
    int idx = blockIdx.x * 256 + threadIdx.x;
    int tok = idx & 255;
    int bc  = idx >> 8;
    int ph = tok >> 4, pw = tok & 15;
    const float* base = x + ((long)bc * NH + ph * 4) * NH + pw * 4;
    float s = 0.f;
#pragma unroll
    for (int r = 0; r < 4; r++) {
        float4 v = *(const float4*)(base + r * NH);
        s += v.x + v.y + v.z + v.w;
    }
    g_xp[idx] = s * 0.0625f;
}

// -------------------- tf32 GEMM, cp.async 4-stage, single-sync pipeline --------------------
// C[m][n] = sum_k A[k][m]*B[k][n]  (both K-major). BN=128, BK=16, 256 threads.
// BM=128: 8 warps 4(M)x2(N), warp tile 32x64 (NT=8), 2 CTAs/SM
// BM= 64: 8 warps 2(M)x4(N), warp tile 32x32 (NT=4), 3 CTAs/SM
// Raw fp32 bits into mma.tf32 (HW truncates mantissa).
// Loop: CPW -> sync -> issue(kb+3) -> compute(kb). The overwritten slot
// (kb+3)&3 == (kb-1)&3 was consumed at kb-1, which every warp finished
// before the sync -> one barrier per iteration is sufficient.
// EPI 0: C=acc  1: +bias[m]  3: +bias[n]  2: +bias[m]+resid + nearest 4x4 upsample
template<int EPI, int BM>
__global__ void __launch_bounds__(256, (BM == 128) ? 2 : 3) mma_gemm(
    const float* __restrict__ Ag, const float* __restrict__ Bg,
    float* __restrict__ Cg, int M, int N, int K,
    int aB, int bB, int cB,
    const float* __restrict__ bias, const float* __restrict__ resid,
    float* __restrict__ dout)
{
    constexpr int ASTR = (BM == 128) ? 136 : 72;   // floats per k-row (pad: 8 mod 32)
    constexpr int BSTR = 136;
    constexpr int STG  = 4;
    constexpr int AFL  = 16 * ASTR;
    constexpr int BFL  = 16 * BSTR;
    constexpr int NT   = (BM == 128) ? 8 : 4;

    extern __shared__ float smem[];                // [STG*AFL | STG*BFL]
    uint32_t su = (uint32_t)__cvta_generic_to_shared(smem);

    int b = blockIdx.z;
    const float* A = Ag + (long)b * aB;
    const float* B = Bg + (long)b * bB;
    int m0 = blockIdx.y * BM, n0 = blockIdx.x << 7;
    int tid  = threadIdx.x;
    int lane = tid & 31, wid = tid >> 5;
    int wm, wn;
    if (BM == 128) { wm = (wid & 3) << 5; wn = (wid >> 2) << 6; }
    else           { wm = (wid & 1) << 5; wn = (wid >> 1) << 5; }
    int lc = lane & 3, lr = lane >> 2;

    int kr = tid >> 4;             // 0..15 staging k-row
    int c4 = (tid & 15) << 2;      // 0..60 staging col (float4)

    uint32_t aw = su + (kr * ASTR + c4) * 4;
    uint32_t bw = su + (STG * AFL + kr * BSTR + c4) * 4;

    float acc[2][NT][4] = {};
    int nk = K >> 4;

    auto issue = [&](int slot, int kb) {
        const float* Ab = A + ((long)(kb << 4) + kr) * M + m0 + c4;
        const float* Bb = B + ((long)(kb << 4) + kr) * N + n0 + c4;
        CPA(aw + slot * (AFL * 4), Ab);
        if (BM == 128) CPA(aw + slot * (AFL * 4) + 256, Ab + 64);
        CPA(bw + slot * (BFL * 4), Bb);
        CPA(bw + slot * (BFL * 4) + 256, Bb + 64);
        CPC();
    };

    issue(0, 0); issue(1, 1); issue(2, 2);

    for (int kb = 0; kb < nk; kb++) {
        CPW(2);
        __syncthreads();
        if (kb + 3 < nk) issue((kb + 3) & 3, kb + 3);
        int slot = kb & 3;
        const uint32_t* Asl = (const uint32_t*)smem + slot * AFL;
        const uint32_t* Bsl = (const uint32_t*)smem + STG * AFL + slot * BFL;
#pragma unroll
        for (int ks = 0; ks < 16; ks += 8) {
            uint32_t fa[2][4];
#pragma unroll
            for (int mt = 0; mt < 2; mt++) {
                int mo = wm + (mt << 4) + lr;
                fa[mt][0] = Asl[(ks + lc) * ASTR + mo];
                fa[mt][1] = Asl[(ks + lc) * ASTR + mo + 8];
                fa[mt][2] = Asl[(ks + lc + 4) * ASTR + mo];
                fa[mt][3] = Asl[(ks + lc + 4) * ASTR + mo + 8];
            }
#pragma unroll
            for (int nt = 0; nt < NT; nt++) {
                int no = wn + (nt << 3) + lr;
                uint32_t fb0 = Bsl[(ks + lc) * BSTR + no];
                uint32_t fb1 = Bsl[(ks + lc + 4) * BSTR + no];
                mma_tf32(acc[0][nt], fa[0][0], fa[0][1], fa[0][2], fa[0][3], fb0, fb1);
                mma_tf32(acc[1][nt], fa[1][0], fa[1][1], fa[1][2], fa[1][3], fb0, fb1);
            }
        }
    }

    if (EPI != 2) {
        float* Cb = Cg + (long)b * cB;
#pragma unroll
        for (int mt = 0; mt < 2; mt++) {
            int r0 = m0 + wm + (mt << 4) + lr;
            float bm0 = 0.f, bm1 = 0.f;
            if (EPI == 1) { bm0 = bias[r0]; bm1 = bias[r0 + 8]; }
#pragma unroll
            for (int nt = 0; nt < NT; nt++) {
                int cn = n0 + wn + (nt << 3) + (lc << 1);
                float bn0 = 0.f, bn1 = 0.f;
                if (EPI == 3) { bn0 = bias[cn]; bn1 = bias[cn + 1]; }
                float2 w0 = make_float2(acc[mt][nt][0] + bm0 + bn0, acc[mt][nt][1] + bm0 + bn1);
                float2 w1 = make_float2(acc[mt][nt][2] + bm1 + bn0, acc[mt][nt][3] + bm1 + bn1);
                *(float2*)(Cb + (long)r0 * N + cn)       = w0;
                *(float2*)(Cb + (long)(r0 + 8) * N + cn) = w1;
            }
        }
    } else {
#pragma unroll
        for (int mt = 0; mt < 2; mt++) {
#pragma unroll
            for (int rr = 0; rr < 2; rr++) {
                int c = m0 + wm + (mt << 4) + lr + (rr << 3);
                float bi = bias[c];
                const float* rrow = resid + ((long)b * NC + c) * NTOK;
                float* crow = dout + ((long)b * NC + c) * (NH * NH);
#pragma unroll
                for (int nt = 0; nt < NT; nt++) {
#pragma unroll
                    for (int jj = 0; jj < 2; jj++) {
                        int tok = n0 + wn + (nt << 3) + (lc << 1) + jj;
                        float v = acc[mt][nt][rr * 2 + jj] + bi + rrow[tok];
                        int ph = tok >> 4, pw = tok & 15;
                        float* o = crow + (ph * 4) * NH + pw * 4;
                        float4 f = make_float4(v, v, v, v);
                        *(float4*)(o)          = f;
                        *(float4*)(o + NH)     = f;
                        *(float4*)(o + 2 * NH) = f;
                        *(float4*)(o + 3 * NH) = f;
                    }
                }
            }
        }
    }
}

// -------------------- transposed softmax --------------------
__global__ void __launch_bounds__(256) softmaxT_k(float* __restrict__ a) {
    int b  = blockIdx.y;
    int i0 = blockIdx.x << 5;
    int t  = threadIdx.x;
    int il = t & 31, jg = t >> 5;
    float* base = a + ((long)b * NTOK) * NTOK + i0 + il;

    float v[32];
    float m = -1e30f;
#pragma unroll
    for (int qj = 0; qj < 32; qj++) {
        v[qj] = base[(long)(jg * 32 + qj) * NTOK];
        m = fmaxf(m, v[qj]);
    }
    __shared__ float red[8][32];
    red[jg][il] = m;
    __syncthreads();
    float mm = red[0][il];
#pragma unroll
    for (int g = 1; g < 8; g++) mm = fmaxf(mm, red[g][il]);
    __syncthreads();

    float s = 0.f;
#pragma unroll
    for (int qj = 0; qj < 32; qj++) {
        v[qj] = __expf(v[qj] - mm);
        s += v[qj];
    }
    red[jg][il] = s;
    __syncthreads();
    float ss = 0.f;
#pragma unroll
    for (int g = 0; g < 8; g++) ss += red[g][il];
    float inv = 1.f / ss;
#pragma unroll
    for (int qj = 0; qj < 32; qj++)
        base[(long)(jg * 32 + qj) * NTOK] = v[qj] * inv;
}

// -------------------- launch --------------------
#define SMEM_128 (4 * (16 * 136 * 4) * 2)                       // 69632 B
#define SMEM_64  (4 * (16 * 72 * 4 + 16 * 136 * 4))             // 53248 B

extern "C" void kernel_launch(void* const* d_in, const int* in_sizes, int n_in,
                              void* d_out, int out_size) {
    (void)in_sizes; (void)n_in; (void)out_size;
    const float* x  = (const float*)d_in[0];
    const float* tw = (const float*)d_in[1];
    const float* tb = (const float*)d_in[2];
    const float* pw = (const float*)d_in[3];
    const float* pb = (const float*)d_in[4];
    const float* gw = (const float*)d_in[5];
    const float* gb = (const float*)d_in[6];
    const float* ow = (const float*)d_in[7];
    const float* ob = (const float*)d_in[8];
    float* out = (float*)d_out;

    float *xp, *Wtp, *gwT, *owT, *btp, *proj, *gT, *attn, *agg;
    cudaGetSymbolAddress((void**)&xp,   g_xp);
    cudaGetSymbolAddress((void**)&Wtp,  g_Wtp);
    cudaGetSymbolAddress((void**)&gwT,  g_gwT);
    cudaGetSymbolAddress((void**)&owT,  g_owT);
    cudaGetSymbolAddress((void**)&btp,  g_btp);
    cudaGetSymbolAddress((void**)&proj, g_proj);
    cudaGetSymbolAddress((void**)&gT,   g_gT);
    cudaGetSymbolAddress((void**)&attn, g_attn);
    cudaGetSymbolAddress((void**)&agg,  g_agg);

    cudaFuncSetAttribute(mma_gemm<1, 128>, cudaFuncAttributeMaxDynamicSharedMemorySize, SMEM_128);
    cudaFuncSetAttribute(mma_gemm<0, 128>, cudaFuncAttributeMaxDynamicSharedMemorySize, SMEM_128);
    cudaFuncSetAttribute(mma_gemm<2, 128>, cudaFuncAttributeMaxDynamicSharedMemorySize, SMEM_128);
    cudaFuncSetAttribute(mma_gemm<3, 64>,  cudaFuncAttributeMaxDynamicSharedMemorySize, SMEM_64);
    cudaFuncSetAttribute(mma_gemm<0, 64>,  cudaFuncAttributeMaxDynamicSharedMemorySize, SMEM_64);

    concat_weights<<<512, 256>>>(tw, tb, pw, pb, gw, ow);
    pool_kernel<<<(NB * NC * NTOK) / 256, 256>>>(x);

    // theta|phi projection: M=256, N=256, K=256; bias over m
    mma_gemm<1, 128><<<dim3(2, 2, NB), 256, SMEM_128>>>(
        Wtp, xp, proj, 256, NTOK, NC, 0, NC * NTOK, 256 * NTOK, btp, nullptr, nullptr);

    // g projection (transposed): gT[b][tok][cc], M=256, N=128, K=256; bias over n
    mma_gemm<3, 64><<<dim3(1, 4, NB), 256, SMEM_64>>>(
        xp, gwT, gT, NTOK, NCI, NC, NC * NTOK, 0, NTOK * NCI, gb, nullptr, nullptr);

    // logitsT: attnT[b][j][i], M=256, N=256, K=128
    mma_gemm<0, 128><<<dim3(2, 2, NB), 256, SMEM_128>>>(
        proj + NCI * NTOK, proj, attn, NTOK, NTOK, NCI,
        256 * NTOK, 256 * NTOK, NTOK * NTOK, nullptr, nullptr, nullptr);

    softmaxT_k<<<dim3(8, NB), 256>>>(attn);

    // agg: aggT[b][cc][i], M=128, N=256, K=256
    mma_gemm<0, 64><<<dim3(2, 2, NB), 256, SMEM_64>>>(
        gT, attn, agg, NCI, NTOK, NTOK,
        NTOK * NCI, NTOK * NTOK, NCI * NTOK, nullptr, nullptr, nullptr);

    // out conv + bias + residual + nearest upsample: M=256, N=256, K=128
    mma_gemm<2, 128><<<dim3(2, 2, NB), 256, SMEM_128>>>(
        owT, agg, nullptr, NC, NTOK, NCI,
        0, NCI * NTOK, 0, ob, xp, out);
}

// round 8
// speedup vs baseline: 1.0331x; 1.0331x over previous
#include <cuda_runtime.h>
#include <cstdint>

// Problem dims (fixed)
#define NB   64
#define NC   256
#define NCI  128
#define NTOK 256
#define NH   64

// -------------------- device scratch --------------------
__device__ float g_xp  [NB * NC  * NTOK];   // pooled [b][c][tok]
__device__ float g_Wtp [NC * 256];          // [c][r]  r = theta|phi
__device__ float g_gwT [NC * NCI];          // [c][cc]
__device__ float g_owT [NCI * NC];          // [cc][C]
__device__ float g_btp [256];
__device__ float g_proj[NB * 256 * NTOK];   // theta|phi, [r][tok]
__device__ float g_gT  [NB * NTOK * NCI];   // [tok][cc]
__device__ float g_attn[NB * NTOK * NTOK];  // attnT [j][i]
__device__ float g_agg [NB * NCI * NTOK];   // aggT [cc][tok]

// -------------------- mma + cp.async helpers --------------------
__device__ __forceinline__ void mma_tf32(float (&c)[4],
                                         uint32_t a0, uint32_t a1, uint32_t a2, uint32_t a3,
                                         uint32_t b0, uint32_t b1) {
    asm volatile(
        "mma.sync.aligned.m16n8k8.row.col.f32.tf32.tf32.f32 "
        "{%0,%1,%2,%3},{%4,%5,%6,%7},{%8,%9},{%0,%1,%2,%3};\n"
        : "+f"(c[0]), "+f"(c[1]), "+f"(c[2]), "+f"(c[3])
        : "r"(a0), "r"(a1), "r"(a2), "r"(a3), "r"(b0), "r"(b1));
}
#define CPA(dst, src) asm volatile("cp.async.cg.shared.global [%0], [%1], 16;" :: "r"(dst), "l"(src))
#define CPC()         asm volatile("cp.async.commit_group;")
#define CPW(n)        asm volatile("cp.async.wait_group %0;" :: "n"(n))

// -------------------- fused pool + weight prep --------------------
// blocks [0, 16384): 4x4 avg pool. blocks [16384, 16896): weight transpose/concat.
#define POOLBLKS ((NB * NC * NTOK) / 256)
__global__ void pool_prep_kernel(const float* __restrict__ x,
                                 const float* __restrict__ tw, const float* __restrict__ tb,
                                 const float* __restrict__ pw, const float* __restrict__ pb,
                                 const float* __restrict__ gw, const float* __restrict__ ow) {
    if (blockIdx.x < POOLBLKS) {
        int idx = blockIdx.x * 256 + threadIdx.x;
        int tok = idx & 255;
        int bc  = idx >> 8;
        int ph = tok >> 4, pw2 = tok & 15;
        const float* base = x + ((long)bc * NH + ph * 4) * NH + pw2 * 4;
        float s = 0.f;
#pragma unroll
        for (int r = 0; r < 4; r++) {
            float4 v = *(const float4*)(base + r * NH);
            s += v.x + v.y + v.z + v.w;
        }
        g_xp[idx] = s * 0.0625f;
    } else {
        int idx = (blockIdx.x - POOLBLKS) * 256 + threadIdx.x;
        if (idx < 65536) {
            int c = idx >> 8, r = idx & 255;
            g_Wtp[idx] = (r < 128) ? tw[r * NC + c] : pw[(r - 128) * NC + c];
            if (idx < 256) g_btp[idx] = (idx < 128) ? tb[idx] : pb[idx - 128];
        } else if (idx < 65536 + 32768) {
            int j = idx - 65536;
            int c = j >> 7, cc = j & 127;
            g_gwT[j] = gw[cc * NC + c];
        } else {
            int j = idx - 65536 - 32768;
            int cc = j >> 8, C = j & 255;
            g_owT[j] = ow[C * NCI + cc];
        }
    }
}

// -------------------- tf32 GEMM, BM=64 x BN=128, cp.async 4-stage --------------------
// C[m][n] = sum_k A[k][m]*B[k][n] (both K-major). 256 threads = 8 warps
// 2(M) x 4(N), warp tile 32x32. 3 CTAs/SM. Single-sync pipeline.
// Raw fp32 bits into mma.tf32 (HW truncates mantissa).
// EPI 0: C=acc  1: +bias[m]  3: +bias[n]  2: +bias[m]+resid + nearest 4x4 upsample
template<int EPI>
__global__ void __launch_bounds__(256, 3) mma_gemm(
    const float* __restrict__ Ag, const float* __restrict__ Bg,
    float* __restrict__ Cg, int M, int N, int K,
    int aB, int bB, int cB,
    const float* __restrict__ bias, const float* __restrict__ resid,
    float* __restrict__ dout)
{
    constexpr int ASTR = 72;      // floats per k-row (64 + pad 8)
    constexpr int BSTR = 136;     // 128 + pad 8
    constexpr int STG  = 4;
    constexpr int AFL  = 16 * ASTR;
    constexpr int BFL  = 16 * BSTR;
    constexpr int NT   = 4;

    extern __shared__ float smem[];
    uint32_t su = (uint32_t)__cvta_generic_to_shared(smem);

    int b = blockIdx.z;
    const float* A = Ag + (long)b * aB;
    const float* B = Bg + (long)b * bB;
    int m0 = blockIdx.y << 6, n0 = blockIdx.x << 7;
    int tid  = threadIdx.x;
    int lane = tid & 31, wid = tid >> 5;
    int wm = (wid & 1) << 5;      // 0,32
    int wn = (wid >> 1) << 5;     // 0,32,64,96
    int lc = lane & 3, lr = lane >> 2;

    int kr = tid >> 4;             // 0..15 staging k-row
    int c4 = (tid & 15) << 2;      // 0..60 staging col

    uint32_t aw = su + (kr * ASTR + c4) * 4;
    uint32_t bw = su + (STG * AFL + kr * BSTR + c4) * 4;

    float acc[2][NT][4] = {};
    int nk = K >> 4;

    auto issue = [&](int slot, int kb) {
        const float* Ab = A + ((long)(kb << 4) + kr) * M + m0 + c4;
        const float* Bb = B + ((long)(kb << 4) + kr) * N + n0 + c4;
        CPA(aw + slot * (AFL * 4), Ab);
        CPA(bw + slot * (BFL * 4), Bb);
        CPA(bw + slot * (BFL * 4) + 256, Bb + 64);
        CPC();
    };

    issue(0, 0); issue(1, 1); issue(2, 2);

    for (int kb = 0; kb < nk; kb++) {
        CPW(2);
        __syncthreads();
        if (kb + 3 < nk) issue((kb + 3) & 3, kb + 3);
        int slot = kb & 3;
        const uint32_t* Asl = (const uint32_t*)smem + slot * AFL;
        const uint32_t* Bsl = (const uint32_t*)smem + STG * AFL + slot * BFL;
#pragma unroll
        for (int ks = 0; ks < 16; ks += 8) {
            uint32_t fa[2][4];
#pragma unroll
            for (int mt = 0; mt < 2; mt++) {
                int mo = wm + (mt << 4) + lr;
                fa[mt][0] = Asl[(ks + lc) * ASTR + mo];
                fa[mt][1] = Asl[(ks + lc) * ASTR + mo + 8];
                fa[mt][2] = Asl[(ks + lc + 4) * ASTR + mo];
                fa[mt][3] = Asl[(ks + lc + 4) * ASTR + mo + 8];
            }
#pragma unroll
            for (int nt = 0; nt < NT; nt++) {
                int no = wn + (nt << 3) + lr;
                uint32_t fb0 = Bsl[(ks + lc) * BSTR + no];
                uint32_t fb1 = Bsl[(ks + lc + 4) * BSTR + no];
                mma_tf32(acc[0][nt], fa[0][0], fa[0][1], fa[0][2], fa[0][3], fb0, fb1);
                mma_tf32(acc[1][nt], fa[1][0], fa[1][1], fa[1][2], fa[1][3], fb0, fb1);
            }
        }
    }

    if (EPI != 2) {
        float* Cb = Cg + (long)b * cB;
#pragma unroll
        for (int mt = 0; mt < 2; mt++) {
            int r0 = m0 + wm + (mt << 4) + lr;
            float bm0 = 0.f, bm1 = 0.f;
            if (EPI == 1) { bm0 = bias[r0]; bm1 = bias[r0 + 8]; }
#pragma unroll
            for (int nt = 0; nt < NT; nt++) {
                int cn = n0 + wn + (nt << 3) + (lc << 1);
                float bn0 = 0.f, bn1 = 0.f;
                if (EPI == 3) { bn0 = bias[cn]; bn1 = bias[cn + 1]; }
                float2 w0 = make_float2(acc[mt][nt][0] + bm0 + bn0, acc[mt][nt][1] + bm0 + bn1);
                float2 w1 = make_float2(acc[mt][nt][2] + bm1 + bn0, acc[mt][nt][3] + bm1 + bn1);
                *(float2*)(Cb + (long)r0 * N + cn)       = w0;
                *(float2*)(Cb + (long)(r0 + 8) * N + cn) = w1;
            }
        }
    } else {
#pragma unroll
        for (int mt = 0; mt < 2; mt++) {
#pragma unroll
            for (int rr = 0; rr < 2; rr++) {
                int c = m0 + wm + (mt << 4) + lr + (rr << 3);
                float bi = bias[c];
                const float* rrow = resid + ((long)b * NC + c) * NTOK;
                float* crow = dout + ((long)b * NC + c) * (NH * NH);
#pragma unroll
                for (int nt = 0; nt < NT; nt++) {
#pragma unroll
                    for (int jj = 0; jj < 2; jj++) {
                        int tok = n0 + wn + (nt << 3) + (lc << 1) + jj;
                        float v = acc[mt][nt][rr * 2 + jj] + bi + rrow[tok];
                        int ph = tok >> 4, pw = tok & 15;
                        float* o = crow + (ph * 4) * NH + pw * 4;
                        float4 f = make_float4(v, v, v, v);
                        *(float4*)(o)          = f;
                        *(float4*)(o + NH)     = f;
                        *(float4*)(o + 2 * NH) = f;
                        *(float4*)(o + 3 * NH) = f;
                    }
                }
            }
        }
    }
}

// -------------------- transposed softmax --------------------
__global__ void __launch_bounds__(256) softmaxT_k(float* __restrict__ a) {
    int b  = blockIdx.y;
    int i0 = blockIdx.x << 5;
    int t  = threadIdx.x;
    int il = t & 31, jg = t >> 5;
    float* base = a + ((long)b * NTOK) * NTOK + i0 + il;

    float v[32];
    float m = -1e30f;
#pragma unroll
    for (int qj = 0; qj < 32; qj++) {
        v[qj] = base[(long)(jg * 32 + qj) * NTOK];
        m = fmaxf(m, v[qj]);
    }
    __shared__ float red[8][32];
    red[jg][il] = m;
    __syncthreads();
    float mm = red[0][il];
#pragma unroll
    for (int g = 1; g < 8; g++) mm = fmaxf(mm, red[g][il]);
    __syncthreads();

    float s = 0.f;
#pragma unroll
    for (int qj = 0; qj < 32; qj++) {
        v[qj] = __expf(v[qj] - mm);
        s += v[qj];
    }
    red[jg][il] = s;
    __syncthreads();
    float ss = 0.f;
#pragma unroll
    for (int g = 0; g < 8; g++) ss += red[g][il];
    float inv = 1.f / ss;
#pragma unroll
    for (int qj = 0; qj < 32; qj++)
        base[(long)(jg * 32 + qj) * NTOK] = v[qj] * inv;
}

// -------------------- launch --------------------
#define SMEM_64 (4 * (16 * 72 * 4 + 16 * 136 * 4))   // 53248 B

extern "C" void kernel_launch(void* const* d_in, const int* in_sizes, int n_in,
                              void* d_out, int out_size) {
    (void)in_sizes; (void)n_in; (void)out_size;
    const float* x  = (const float*)d_in[0];
    const float* tw = (const float*)d_in[1];
    const float* tb = (const float*)d_in[2];
    const float* pw = (const float*)d_in[3];
    const float* pb = (const float*)d_in[4];
    const float* gw = (const float*)d_in[5];
    const float* gb = (const float*)d_in[6];
    const float* ow = (const float*)d_in[7];
    const float* ob = (const float*)d_in[8];
    float* out = (float*)d_out;

    float *xp, *Wtp, *gwT, *owT, *btp, *proj, *gT, *attn, *agg;
    cudaGetSymbolAddress((void**)&xp,   g_xp);
    cudaGetSymbolAddress((void**)&Wtp,  g_Wtp);
    cudaGetSymbolAddress((void**)&gwT,  g_gwT);
    cudaGetSymbolAddress((void**)&owT,  g_owT);
    cudaGetSymbolAddress((void**)&btp,  g_btp);
    cudaGetSymbolAddress((void**)&proj, g_proj);
    cudaGetSymbolAddress((void**)&gT,   g_gT);
    cudaGetSymbolAddress((void**)&attn, g_attn);
    cudaGetSymbolAddress((void**)&agg,  g_agg);

    cudaFuncSetAttribute(mma_gemm<0>, cudaFuncAttributeMaxDynamicSharedMemorySize, SMEM_64);
    cudaFuncSetAttribute(mma_gemm<1>, cudaFuncAttributeMaxDynamicSharedMemorySize, SMEM_64);
    cudaFuncSetAttribute(mma_gemm<2>, cudaFuncAttributeMaxDynamicSharedMemorySize, SMEM_64);
    cudaFuncSetAttribute(mma_gemm<3>, cudaFuncAttributeMaxDynamicSharedMemorySize, SMEM_64);

    // pool + weight prep fused (16384 pool blocks + 512 prep blocks)
    pool_prep_kernel<<<POOLBLKS + 512, 256>>>(x, tw, tb, pw, pb, gw, ow);

    // theta|phi projection: M=256, N=256, K=256; bias over m — grid 512
    mma_gemm<1><<<dim3(2, 4, NB), 256, SMEM_64>>>(
        Wtp, xp, proj, 256, NTOK, NC, 0, NC * NTOK, 256 * NTOK, btp, nullptr, nullptr);

    // g projection (transposed): gT[b][tok][cc], M=256, N=128, K=256; bias over n — grid 256
    mma_gemm<3><<<dim3(1, 4, NB), 256, SMEM_64>>>(
        xp, gwT, gT, NTOK, NCI, NC, NC * NTOK, 0, NTOK * NCI, gb, nullptr, nullptr);

    // logitsT: attnT[b][j][i], M=256, N=256, K=128 — grid 512
    mma_gemm<0><<<dim3(2, 4, NB), 256, SMEM_64>>>(
        proj + NCI * NTOK, proj, attn, NTOK, NTOK, NCI,
        256 * NTOK, 256 * NTOK, NTOK * NTOK, nullptr, nullptr, nullptr);

    softmaxT_k<<<dim3(8, NB), 256>>>(attn);

    // agg: aggT[b][cc][i], M=128, N=256, K=256 — grid 256
    mma_gemm<0><<<dim3(2, 2, NB), 256, SMEM_64>>>(
        gT, attn, agg, NCI, NTOK, NTOK,
        NTOK * NCI, NTOK * NTOK, NCI * NTOK, nullptr, nullptr, nullptr);

    // out conv + bias + residual + nearest upsample: M=256, N=256, K=128 — grid 512
    mma_gemm<2><<<dim3(2, 4, NB), 256, SMEM_64>>>(
        owT, agg, nullptr, NC, NTOK, NCI,
        0, NCI * NTOK, 0, ob, xp, out);
}